// round 15
// baseline (speedup 1.0000x reference)
#include <cuda_runtime.h>
#include <cstdint>

#define TT 30
#define DTc 0.03f

// ---------------- device scratch (static, no runtime alloc) ----------------
__device__ float4 g_Me4[256];           // fused input matrix enc: row r, 4 cols
__device__ float4 g_Md4[256];
__device__ float  g_be[256];            // fused bias enc
__device__ float  g_bd[256];
__device__ float  g_Wcell[2][17408];    // [m][cell j][gate g][k 0..67]
__device__ float  g_biasCell[2][256];   // [m][j*4+g]
__device__ float  g_hT[16384 * 64];
__device__ float  g_dh[16384 * 64];

// ---------------- helpers ----------------
static __device__ __forceinline__ unsigned long long pk2(float lo, float hi) {
    unsigned long long r;
    asm("mov.b64 %0, {%1, %2};" : "=l"(r)
        : "r"(__float_as_uint(lo)), "r"(__float_as_uint(hi)));
    return r;
}
static __device__ __forceinline__ void upk2(unsigned long long v, float& lo, float& hi) {
    unsigned int a, b;
    asm("mov.b64 {%0, %1}, %2;" : "=r"(a), "=r"(b) : "l"(v));
    lo = __uint_as_float(a); hi = __uint_as_float(b);
}
// packed f32x2 FMA (Blackwell; ptxas never emits this from C++)
static __device__ __forceinline__ unsigned long long fma2(unsigned long long a,
                                                          unsigned long long b,
                                                          unsigned long long c) {
    unsigned long long d;
    asm("fma.rn.f32x2 %0, %1, %2, %3;" : "=l"(d) : "l"(a), "l"(b), "l"(c));
    return d;
}
static __device__ __forceinline__ float sigf(float x) {
    return __fdividef(1.0f, 1.0f + __expf(-x));
}
static __device__ __forceinline__ float tanhfx(float x) {
    float e = __expf(2.0f * x);
    return 1.0f - __fdividef(2.0f, e + 1.0f);
}
static __device__ __forceinline__ float leaky(float x) {
    return x >= 0.0f ? x : 0.01f * x;
}

// ---------------- prep1: fuse W_se into W_ih ----------------
__global__ void prep1_kernel(const float* __restrict__ Wse, const float* __restrict__ bse,
                             const float* __restrict__ Wih_e,
                             const float* __restrict__ bih_e, const float* __restrict__ bhh_e,
                             const float* __restrict__ Wih_d,
                             const float* __restrict__ bih_d, const float* __restrict__ bhh_d) {
    int r = threadIdx.x;  // 256 threads, r = gate row 0..255
    {
        float m0 = 0, m1 = 0, m2 = 0, m3 = 0, bb = 0;
        for (int k = 0; k < 64; k++) {
            float wv = Wih_e[r * 64 + k];
            bb += wv * bse[k];
            m0 += wv * Wse[k * 4 + 0]; m1 += wv * Wse[k * 4 + 1];
            m2 += wv * Wse[k * 4 + 2]; m3 += wv * Wse[k * 4 + 3];
        }
        g_Me4[r] = make_float4(m0, m1, m2, m3);
        g_be[r] = bb + bih_e[r] + bhh_e[r];
    }
    {
        float m0 = 0, m1 = 0, m2 = 0, m3 = 0, bb = 0;
        for (int k = 0; k < 64; k++) {
            float wv = Wih_d[r * 64 + k];
            bb += wv * bse[k];
            m0 += wv * Wse[k * 4 + 0]; m1 += wv * Wse[k * 4 + 1];
            m2 += wv * Wse[k * 4 + 2]; m3 += wv * Wse[k * 4 + 3];
        }
        g_Md4[r] = make_float4(m0, m1, m2, m3);
        g_bd[r] = bb + bih_d[r] + bhh_d[r];
    }
}

// ---------------- prep3: cell-major extended weight layout ----------------
// g_Wcell[m][((j*4)+g)*68 + k]: k<64 -> Whh[g*64+j][k]; k-64 -> fused input col.
__global__ void prep3_kernel(const float* __restrict__ Whh_e, const float* __restrict__ Whh_d) {
    int gid = blockIdx.x * blockDim.x + threadIdx.x;
    if (gid < 2 * 17408) {
        int m = gid / 17408, rest = gid % 17408;
        int j = rest / 272, r2 = rest % 272;
        int g = r2 / 68, k = r2 % 68;
        const float* Whh = m ? Whh_d : Whh_e;
        const float4* Mx = m ? g_Md4 : g_Me4;
        int row = g * 64 + j;
        float w = (k < 64) ? Whh[row * 64 + k] : ((const float*)&Mx[row])[k - 64];
        g_Wcell[m][rest] = w;
    }
    if (gid < 2 * 256) {
        int m = gid / 256, rr = gid % 256;
        int j = rr / 4, g = rr % 4;
        g_biasCell[m][rr] = (m ? g_bd : g_be)[g * 64 + j];
    }
}

// ======================= per-thread-recurrence LSTM =========================
// block = 128 threads = 128 batch elems; grid = B/128. Thread e owns elem e:
// state s2[34] = 68-dim (h|x) vector as f32x2 pairs in REGISTERS; c and h_new
// live in per-thread smem columns (dynamic j indexing). Weights are a shared
// 68KB tile; every lane reads the SAME address -> broadcast LDS.128 feeding
// 8 fma2 per 4 weight-loads. NO barriers/shuffles inside the time loop.
// smem floats: W 17408 | bias 256 | Wc 128 | c 64*128 | hn(pairs) 32*128*2
#define OFF_B_  17408
#define OFF_WC_ 17664
#define OFF_C_  17792
#define OFF_HN_ 25984
#define SMEM_PT ((25984 + 8192) * 4)

template <bool DEC>
__global__ void __launch_bounds__(128) lstm_pt_kernel(
    const float* __restrict__ traj, const float* __restrict__ init_state,
    const float* __restrict__ Wc, const float* __restrict__ bc,
    float* __restrict__ out, int B) {
    extern __shared__ float sm[];
    float* Wsh = sm;
    float* Bsh = sm + OFF_B_;
    float* WcSh = sm + OFF_WC_;
    float* cShb = sm + OFF_C_;
    unsigned long long* hnp = (unsigned long long*)(sm + OFF_HN_);

    const int tid = threadIdx.x;
    const int e = blockIdx.x * 128 + tid;

    {
        const float* gw = g_Wcell[DEC ? 1 : 0];
        for (int i = tid; i < 17408; i += 128) Wsh[i] = gw[i];
        const float* gb = g_biasCell[DEC ? 1 : 0];
        Bsh[tid] = gb[tid]; Bsh[128 + tid] = gb[128 + tid];
        if (DEC) WcSh[tid] = Wc[tid];   // [w][k] rows of 64
    }

    unsigned long long s2[34];
    float bc0 = 0.f, bc1 = 0.f, px = 0.f, py = 0.f;
    if (DEC) {
        bc0 = bc[0]; bc1 = bc[1];
        const ulonglong2* dh2 = (const ulonglong2*)(g_dh + (size_t)e * 64);
#pragma unroll
        for (int q = 0; q < 16; q++) {
            ulonglong2 v = dh2[q];
            s2[2 * q] = v.x; s2[2 * q + 1] = v.y;
        }
#pragma unroll
        for (int p = 0; p < 32; p++) {
            float lo, hi; upk2(s2[p], lo, hi);
            cShb[(2 * p) * 128 + tid] = lo;
            cShb[(2 * p + 1) * 128 + tid] = hi;
        }
        float4 iv = *(const float4*)(init_state + (size_t)e * 4);
        s2[32] = pk2(iv.x, iv.y); s2[33] = pk2(iv.z, iv.w);
    } else {
#pragma unroll
        for (int p = 0; p < 32; p++) s2[p] = 0ull;
#pragma unroll
        for (int j = 0; j < 64; j++) cShb[j * 128 + tid] = 0.f;
        float4 cv = *(const float4*)(traj + (size_t)e * 120);
        s2[32] = pk2(cv.x, cv.y); s2[33] = pk2(cv.z, cv.w);  // t=0: raw xy
        px = cv.x; py = cv.y;
    }
    __syncthreads();

    for (int t = 0; t < TT; t++) {
#pragma unroll 2
        for (int j = 0; j < 64; j++) {
            const ulonglong2* w0 = (const ulonglong2*)(Wsh + j * 272);
            const ulonglong2* w1 = (const ulonglong2*)(Wsh + j * 272 + 68);
            const ulonglong2* w2 = (const ulonglong2*)(Wsh + j * 272 + 136);
            const ulonglong2* w3 = (const ulonglong2*)(Wsh + j * 272 + 204);
            unsigned long long a0 = 0ull, a1 = 0ull, a2 = 0ull, a3 = 0ull;
#pragma unroll
            for (int kk = 0; kk < 17; kk++) {
                ulonglong2 wa = w0[kk], wb = w1[kk], wcv = w2[kk], wd = w3[kk];
                unsigned long long sA = s2[2 * kk], sB = s2[2 * kk + 1];
                a0 = fma2(wa.x, sA, a0); a0 = fma2(wa.y, sB, a0);
                a1 = fma2(wb.x, sA, a1); a1 = fma2(wb.y, sB, a1);
                a2 = fma2(wcv.x, sA, a2); a2 = fma2(wcv.y, sB, a2);
                a3 = fma2(wd.x, sA, a3); a3 = fma2(wd.y, sB, a3);
            }
            float4 bv = *(const float4*)(Bsh + j * 4);
            float t0, t1;
            upk2(a0, t0, t1); float gi = t0 + t1 + bv.x;
            upk2(a1, t0, t1); float gf = t0 + t1 + bv.y;
            upk2(a2, t0, t1); float gg = t0 + t1 + bv.z;
            upk2(a3, t0, t1); float go = t0 + t1 + bv.w;
            float cold = cShb[j * 128 + tid];
            float cn = sigf(gf) * cold + sigf(gi) * tanhfx(gg);
            float h = sigf(go) * tanhfx(cn);
            cShb[j * 128 + tid] = cn;
            ((float*)(hnp + (j >> 1) * 128 + tid))[j & 1] = h;
        }
        // pull new h pairs back into registers (own column, no sync needed)
#pragma unroll
        for (int p = 0; p < 32; p++) s2[p] = hnp[p * 128 + tid];

        if (DEC) {
            unsigned long long ca0 = 0ull, ca1 = 0ull;
            const unsigned long long* wcp0 = (const unsigned long long*)WcSh;
            const unsigned long long* wcp1 = (const unsigned long long*)(WcSh + 64);
#pragma unroll
            for (int p = 0; p < 32; p++) {
                ca0 = fma2(wcp0[p], s2[p], ca0);
                ca1 = fma2(wcp1[p], s2[p], ca1);
            }
            float l0, h0, l1, h1;
            upk2(ca0, l0, h0); upk2(ca1, l1, h1);
            float pedal = l0 + h0 + bc0;
            float steer = fminf(fmaxf(l1 + h1 + bc1, -0.5f), 0.5f);
            float xx, xy, xz, xw;
            upk2(s2[32], xx, xy); upk2(s2[33], xz, xw);
            float v1 = fminf(fmaxf(xw + pedal * DTc, 0.0f), 30.0f);
            float pd = fminf(fmaxf(xw * __tanf(steer) * 0.4f, -1.57f), 1.57f);
            float sn, cs;
            __sincosf(xz, &sn, &cs);
            float nx = xx + xw * cs * DTc;
            float ny = xy + xw * sn * DTc;
            float nz = xz + pd * DTc;
            *(float4*)(out + (size_t)e * 120 + t * 4) = make_float4(nx, ny, nz, v1);
            s2[32] = pk2(nx, ny); s2[33] = pk2(nz, v1);
        } else if (t + 1 < TT) {
            float4 cv = *(const float4*)(traj + (size_t)e * 120 + (t + 1) * 4);
            s2[32] = pk2(cv.x - px, cv.y - py); s2[33] = pk2(cv.z, cv.w);
            px = cv.x; py = cv.y;
        }
    }

    if (!DEC) {
        ulonglong2* dst = (ulonglong2*)(g_hT + (size_t)e * 64);
#pragma unroll
        for (int q = 0; q < 16; q++) dst[q] = make_ulonglong2(s2[2 * q], s2[2 * q + 1]);
    }
}

// ---------------- MLPs + reparam + decoder-init (unchanged, passing) -------
#define NBm 16
__global__ void __launch_bounds__(128) mlp_kernel(
    const float* __restrict__ eps,
    const float* __restrict__ mWs, const float* __restrict__ mbs,
    const float* __restrict__ mWf, const float* __restrict__ mbf,
    const float* __restrict__ lWs, const float* __restrict__ lbs,
    const float* __restrict__ lWf, const float* __restrict__ lbf,
    const float* __restrict__ Winit, const float* __restrict__ binit,
    float* __restrict__ out, int B) {
    __shared__ float hb[2][2][64][20];
    __shared__ float fo_sh[2][104][NBm];
    __shared__ float z_sh[NBm][104];

    const int tid = threadIdx.x;
    const int path = tid >> 6, j = tid & 63;
    const int b0 = blockIdx.x * NBm;

    for (int idx = tid; idx < 2048; idx += 128) {
        int p_ = idx >> 10, rest = idx & 1023;
        int e = rest >> 6, k = rest & 63;
        hb[0][p_][k][e] = g_hT[(size_t)(b0 + e) * 64 + k];
    }
    __syncthreads();

    const float* Ws = path ? lWs : mWs;
    const float* bs = path ? lbs : mbs;
    const float* Wf = path ? lWf : mWf;
    const float* bf = path ? lbf : mbf;

    int pp = 0;
    for (int L3 = 0; L3 < 3; L3++) {
        float acc[NBm];
        float bias = bs[L3 * 64 + j];
#pragma unroll
        for (int e = 0; e < NBm; e++) acc[e] = bias;
        const float4* Wr = (const float4*)(Ws + L3 * 4096 + j * 64);
#pragma unroll
        for (int k4 = 0; k4 < 16; k4++) {
            float4 w = Wr[k4];
#pragma unroll
            for (int kk = 0; kk < 4; kk++) {
                int k = k4 * 4 + kk;
                float wv = (&w.x)[kk];
                float4 h0 = *(const float4*)&hb[pp][path][k][0];
                float4 h1 = *(const float4*)&hb[pp][path][k][4];
                float4 h2 = *(const float4*)&hb[pp][path][k][8];
                float4 h3 = *(const float4*)&hb[pp][path][k][12];
                acc[0] += wv * h0.x; acc[1] += wv * h0.y; acc[2] += wv * h0.z; acc[3] += wv * h0.w;
                acc[4] += wv * h1.x; acc[5] += wv * h1.y; acc[6] += wv * h1.z; acc[7] += wv * h1.w;
                acc[8] += wv * h2.x; acc[9] += wv * h2.y; acc[10] += wv * h2.z; acc[11] += wv * h2.w;
                acc[12] += wv * h3.x; acc[13] += wv * h3.y; acc[14] += wv * h3.z; acc[15] += wv * h3.w;
            }
        }
#pragma unroll
        for (int e = 0; e < NBm; e++) hb[pp ^ 1][path][j][e] = leaky(acc[e]);
        __syncthreads();
        pp ^= 1;
    }

    {
        const size_t muOff = (size_t)2 * B * 120 + (size_t)path * B * 100;
        int o2 = j + 64;
        bool v2 = (o2 < 100);
        float a1[NBm], a2[NBm];
        float b1 = bf[j], b2 = v2 ? bf[o2] : 0.0f;
#pragma unroll
        for (int e = 0; e < NBm; e++) { a1[e] = b1; a2[e] = b2; }
        const float4* W1 = (const float4*)(Wf + j * 64);
        const float4* W2 = (const float4*)(Wf + (v2 ? o2 : j) * 64);
#pragma unroll
        for (int k4 = 0; k4 < 16; k4++) {
            float4 w1 = W1[k4], w2 = W2[k4];
#pragma unroll
            for (int kk = 0; kk < 4; kk++) {
                int k = k4 * 4 + kk;
                float wv1 = (&w1.x)[kk], wv2 = (&w2.x)[kk];
#pragma unroll
                for (int q = 0; q < 4; q++) {
                    float4 hq = *(const float4*)&hb[pp][path][k][q * 4];
                    a1[q * 4 + 0] += wv1 * hq.x; a1[q * 4 + 1] += wv1 * hq.y;
                    a1[q * 4 + 2] += wv1 * hq.z; a1[q * 4 + 3] += wv1 * hq.w;
                    a2[q * 4 + 0] += wv2 * hq.x; a2[q * 4 + 1] += wv2 * hq.y;
                    a2[q * 4 + 2] += wv2 * hq.z; a2[q * 4 + 3] += wv2 * hq.w;
                }
            }
        }
#pragma unroll
        for (int e = 0; e < NBm; e++) {
            float f1 = leaky(a1[e]);
            fo_sh[path][j][e] = f1;
            out[muOff + (size_t)(b0 + e) * 100 + j] = f1;
            if (v2) {
                float f2 = leaky(a2[e]);
                fo_sh[path][o2][e] = f2;
                out[muOff + (size_t)(b0 + e) * 100 + o2] = f2;
            }
        }
    }
    __syncthreads();

    for (int idx = tid; idx < NBm * 100; idx += 128) {
        int e = idx / 100, o = idx - e * 100;
        float mu = fo_sh[0][o][e], lv = fo_sh[1][o][e];
        z_sh[e][o] = tanhfx(eps[(size_t)(b0 + e) * 100 + o] * __expf(0.5f * lv) + mu);
    }
    __syncthreads();

    {
        int half = tid >> 6;
        float acc8[8];
        float bi = binit[j];
#pragma unroll
        for (int e = 0; e < 8; e++) acc8[e] = bi;
        const float4* Wr = (const float4*)(Winit + j * 100);
#pragma unroll
        for (int o4 = 0; o4 < 25; o4++) {
            float4 w = Wr[o4];
#pragma unroll
            for (int e = 0; e < 8; e++) {
                float4 zv = *(const float4*)&z_sh[half * 8 + e][o4 * 4];
                acc8[e] += w.x * zv.x + w.y * zv.y + w.z * zv.z + w.w * zv.w;
            }
        }
#pragma unroll
        for (int e = 0; e < 8; e++)
            g_dh[(size_t)(b0 + half * 8 + e) * 64 + j] = acc8[e];
    }
}

// ---------------- launch ----------------
extern "C" void kernel_launch(void* const* d_in, const int* in_sizes, int n_in,
                              void* d_out, int out_size) {
    const float* traj   = (const float*)d_in[0];
    const float* init   = (const float*)d_in[1];
    const float* eps    = (const float*)d_in[2];
    const float* Wse    = (const float*)d_in[3];
    const float* bse    = (const float*)d_in[4];
    const float* Wih_e  = (const float*)d_in[5];
    const float* Whh_e  = (const float*)d_in[6];
    const float* bih_e  = (const float*)d_in[7];
    const float* bhh_e  = (const float*)d_in[8];
    const float* mWs    = (const float*)d_in[9];
    const float* mbs    = (const float*)d_in[10];
    const float* mWf    = (const float*)d_in[11];
    const float* mbf    = (const float*)d_in[12];
    const float* lWs    = (const float*)d_in[13];
    const float* lbs    = (const float*)d_in[14];
    const float* lWf    = (const float*)d_in[15];
    const float* lbf    = (const float*)d_in[16];
    const float* Winit  = (const float*)d_in[17];
    const float* binit  = (const float*)d_in[18];
    const float* Wih_d  = (const float*)d_in[19];
    const float* Whh_d  = (const float*)d_in[20];
    const float* bih_d  = (const float*)d_in[21];
    const float* bhh_d  = (const float*)d_in[22];
    const float* Wc     = (const float*)d_in[23];
    const float* bc     = (const float*)d_in[24];
    float* out = (float*)d_out;

    int B = in_sizes[0] / 120;  // (B, 30, 4)

    // Unconditional, idempotent: no static guards (harness rule).
    (void)cudaFuncSetAttribute(lstm_pt_kernel<false>,
                               cudaFuncAttributeMaxDynamicSharedMemorySize, SMEM_PT);
    (void)cudaFuncSetAttribute(lstm_pt_kernel<true>,
                               cudaFuncAttributeMaxDynamicSharedMemorySize, SMEM_PT);

    prep1_kernel<<<1, 256>>>(Wse, bse, Wih_e, bih_e, bhh_e, Wih_d, bih_d, bhh_d);
    prep3_kernel<<<(2 * 17408 + 255) / 256, 256>>>(Whh_e, Whh_d);
    lstm_pt_kernel<false><<<B / 128, 128, SMEM_PT>>>(traj, nullptr, nullptr, nullptr,
                                                     out, B);
    mlp_kernel<<<B / NBm, 128>>>(eps, mWs, mbs, mWf, mbf, lWs, lbs, lWf, lbf,
                                 Winit, binit, out, B);
    lstm_pt_kernel<true><<<B / 128, 128, SMEM_PT>>>(nullptr, init, Wc, bc, out, B);
    // expert_traj passthrough (output slot 2)
    cudaMemcpyAsync(out + (size_t)B * 120, traj, (size_t)B * 120 * sizeof(float),
                    cudaMemcpyDeviceToDevice);
}

// round 17
// speedup vs baseline: 2.5040x; 2.5040x over previous
#include <cuda_runtime.h>

#define TT 30
#define DTc 0.03f

// ---------------- device scratch (static, no runtime alloc) ----------------
__device__ float4 g_Whh4_e[64 * 64];   // [k][j] -> rows (j, 64+j, 128+j, 192+j) at col k
__device__ float4 g_Whh4_d[64 * 64];
__device__ float4 g_Me4[256];          // fused input matrix enc: row r, 4 cols
__device__ float4 g_Md4[256];
__device__ float  g_be[256];           // fused bias enc
__device__ float  g_bd[256];
__device__ float  g_hT[16384 * 64];
__device__ float  g_dh[16384 * 64];

// ---------------- helpers ----------------
static __device__ __forceinline__ unsigned long long pk2(float lo, float hi) {
    unsigned long long r;
    asm("mov.b64 %0, {%1, %2};" : "=l"(r)
        : "r"(__float_as_uint(lo)), "r"(__float_as_uint(hi)));
    return r;
}
static __device__ __forceinline__ void upk2(unsigned long long v, float& lo, float& hi) {
    unsigned int a, b;
    asm("mov.b64 {%0, %1}, %2;" : "=r"(a), "=r"(b) : "l"(v));
    lo = __uint_as_float(a); hi = __uint_as_float(b);
}
// packed f32x2 FMA (Blackwell; ptxas never emits this from C++)
static __device__ __forceinline__ unsigned long long fma2(unsigned long long a,
                                                          unsigned long long b,
                                                          unsigned long long c) {
    unsigned long long d;
    asm("fma.rn.f32x2 %0, %1, %2, %3;" : "=l"(d) : "l"(a), "l"(b), "l"(c));
    return d;
}
static __device__ __forceinline__ float sigf(float x) {
    return __fdividef(1.0f, 1.0f + __expf(-x));
}
static __device__ __forceinline__ float tanhfx(float x) {
    float e = __expf(2.0f * x);
    return 1.0f - __fdividef(2.0f, e + 1.0f);
}
static __device__ __forceinline__ float leaky(float x) {
    return x >= 0.0f ? x : 0.01f * x;
}

// ---------------- prep: fuse W_se into W_ih, transpose W_hh ----------------
__global__ void prep_kernel(const float* __restrict__ Wse, const float* __restrict__ bse,
                            const float* __restrict__ Wih_e, const float* __restrict__ Whh_e,
                            const float* __restrict__ bih_e, const float* __restrict__ bhh_e,
                            const float* __restrict__ Wih_d, const float* __restrict__ Whh_d,
                            const float* __restrict__ bih_d, const float* __restrict__ bhh_d) {
    int r = threadIdx.x;  // 256 threads, r = gate row 0..255
    {
        float m0 = 0, m1 = 0, m2 = 0, m3 = 0, bb = 0;
        for (int k = 0; k < 64; k++) {
            float wv = Wih_e[r * 64 + k];
            bb += wv * bse[k];
            m0 += wv * Wse[k * 4 + 0]; m1 += wv * Wse[k * 4 + 1];
            m2 += wv * Wse[k * 4 + 2]; m3 += wv * Wse[k * 4 + 3];
        }
        g_Me4[r] = make_float4(m0, m1, m2, m3);
        g_be[r] = bb + bih_e[r] + bhh_e[r];
    }
    {
        float m0 = 0, m1 = 0, m2 = 0, m3 = 0, bb = 0;
        for (int k = 0; k < 64; k++) {
            float wv = Wih_d[r * 64 + k];
            bb += wv * bse[k];
            m0 += wv * Wse[k * 4 + 0]; m1 += wv * Wse[k * 4 + 1];
            m2 += wv * Wse[k * 4 + 2]; m3 += wv * Wse[k * 4 + 3];
        }
        g_Md4[r] = make_float4(m0, m1, m2, m3);
        g_bd[r] = bb + bih_d[r] + bhh_d[r];
    }
    for (int idx = r; idx < 4096; idx += 256) {
        int k = idx >> 6, jj = idx & 63;
        g_Whh4_e[idx] = make_float4(Whh_e[jj * 64 + k], Whh_e[(64 + jj) * 64 + k],
                                    Whh_e[(128 + jj) * 64 + k], Whh_e[(192 + jj) * 64 + k]);
        g_Whh4_d[idx] = make_float4(Whh_d[jj * 64 + k], Whh_d[(64 + jj) * 64 + k],
                                    Whh_d[(128 + jj) * 64 + k], Whh_d[(192 + jj) * 64 + k]);
    }
}

// ---------------- encoder LSTM ----------------
// block = 256 threads = 4 groups x 64 threads; each group handles 8 batch elems,
// thread j computes gate-dim j for all 8 elems via f32x2 pairs.
// R1 inner loop (float4 weights + dup movs) + double-buffered h -> 1 bar/step.
__global__ void __launch_bounds__(256, 2) enc_kernel(const float* __restrict__ traj, int B) {
    __shared__ unsigned long long h_sh[2][4][64][4];  // [buf][group][dim][pair]
    __shared__ float4 inp_sh[2][4][8];

    const int tid = threadIdx.x, g = tid >> 6, j = tid & 63;
    const int base = blockIdx.x * 32 + g * 8;

    float c[8], hv[8];
#pragma unroll
    for (int e = 0; e < 8; e++) c[e] = 0.0f;
#pragma unroll
    for (int p = 0; p < 4; p++) h_sh[0][g][j][p] = pk2(0.0f, 0.0f);

    float px = 0.0f, py = 0.0f;
    if (j < 8) {
        const float* tp = traj + (size_t)(base + j) * 120;
        float4 cv = *(const float4*)tp;
        inp_sh[0][g][j] = cv;  // t=0: raw xy
        px = cv.x; py = cv.y;
    }
    __syncthreads();

    for (int t = 0; t < TT; t++) {
        const int cur = t & 1, nxt = cur ^ 1;
        unsigned long long acc[4][4];
        {
            float me0[4], me1[4], me2[4], me3[4], bb[4];
#pragma unroll
            for (int r = 0; r < 4; r++) {
                float4 m = g_Me4[r * 64 + j];
                me0[r] = m.x; me1[r] = m.y; me2[r] = m.z; me3[r] = m.w;
                bb[r] = g_be[r * 64 + j];
            }
#pragma unroll
            for (int p = 0; p < 4; p++) {
                float4 i0 = inp_sh[cur][g][2 * p], i1 = inp_sh[cur][g][2 * p + 1];
#pragma unroll
                for (int r = 0; r < 4; r++) {
                    float a0 = bb[r] + me0[r] * i0.x + me1[r] * i0.y + me2[r] * i0.z + me3[r] * i0.w;
                    float a1 = bb[r] + me0[r] * i1.x + me1[r] * i1.y + me2[r] * i1.z + me3[r] * i1.w;
                    acc[r][p] = pk2(a0, a1);
                }
            }
        }
#pragma unroll 8
        for (int k = 0; k < 64; k++) {
            float4 w = g_Whh4_e[k * 64 + j];
            unsigned long long w0 = pk2(w.x, w.x), w1 = pk2(w.y, w.y);
            unsigned long long w2 = pk2(w.z, w.z), w3 = pk2(w.w, w.w);
            ulonglong2 hAB = *(const ulonglong2*)&h_sh[cur][g][k][0];
            ulonglong2 hCD = *(const ulonglong2*)&h_sh[cur][g][k][2];
            unsigned long long hp[4] = {hAB.x, hAB.y, hCD.x, hCD.y};
#pragma unroll
            for (int p = 0; p < 4; p++) {
                acc[0][p] = fma2(w0, hp[p], acc[0][p]);
                acc[1][p] = fma2(w1, hp[p], acc[1][p]);
                acc[2][p] = fma2(w2, hp[p], acc[2][p]);
                acc[3][p] = fma2(w3, hp[p], acc[3][p]);
            }
        }
#pragma unroll
        for (int p = 0; p < 4; p++) {
            float i0, i1, f0, f1, g0, g1, o0, o1;
            upk2(acc[0][p], i0, i1); upk2(acc[1][p], f0, f1);
            upk2(acc[2][p], g0, g1); upk2(acc[3][p], o0, o1);
            int e = 2 * p;
            float cn = sigf(f0) * c[e] + sigf(i0) * tanhfx(g0);
            hv[e] = sigf(o0) * tanhfx(cn); c[e] = cn;
            e++;
            cn = sigf(f1) * c[e] + sigf(i1) * tanhfx(g1);
            hv[e] = sigf(o1) * tanhfx(cn); c[e] = cn;
        }
#pragma unroll
        for (int p = 0; p < 4; p++) h_sh[nxt][g][j][p] = pk2(hv[2 * p], hv[2 * p + 1]);
        if (j < 8 && t + 1 < TT) {
            const float* tp = traj + (size_t)(base + j) * 120 + (t + 1) * 4;
            float4 cv = *(const float4*)tp;
            inp_sh[nxt][g][j] = make_float4(cv.x - px, cv.y - py, cv.z, cv.w);
            px = cv.x; py = cv.y;
        }
        __syncthreads();
    }
#pragma unroll
    for (int e = 0; e < 8; e++) g_hT[(size_t)(base + e) * 64 + j] = hv[e];
}

// ---------------- MLPs + reparam + decoder-init ----------------
// block = 128 threads = 2 paths x 64 dims; each block handles 16 batch elems.
#define NBm 16
__global__ void __launch_bounds__(128) mlp_kernel(
    const float* __restrict__ eps,
    const float* __restrict__ mWs, const float* __restrict__ mbs,
    const float* __restrict__ mWf, const float* __restrict__ mbf,
    const float* __restrict__ lWs, const float* __restrict__ lbs,
    const float* __restrict__ lWf, const float* __restrict__ lbf,
    const float* __restrict__ Winit, const float* __restrict__ binit,
    float* __restrict__ out, int B) {
    __shared__ float hb[2][2][64][20];      // [pingpong][path][k][elem] (pad 20)
    __shared__ float fo_sh[2][104][NBm];    // [path][o][elem]
    __shared__ float z_sh[NBm][104];

    const int tid = threadIdx.x;
    const int path = tid >> 6, j = tid & 63;
    const int b0 = blockIdx.x * NBm;

    for (int idx = tid; idx < 2048; idx += 128) {
        int p_ = idx >> 10, rest = idx & 1023;
        int e = rest >> 6, k = rest & 63;
        hb[0][p_][k][e] = g_hT[(size_t)(b0 + e) * 64 + k];
    }
    __syncthreads();

    const float* Ws = path ? lWs : mWs;
    const float* bs = path ? lbs : mbs;
    const float* Wf = path ? lWf : mWf;
    const float* bf = path ? lbf : mbf;

    int pp = 0;
    for (int L3 = 0; L3 < 3; L3++) {
        float acc[NBm];
        float bias = bs[L3 * 64 + j];
#pragma unroll
        for (int e = 0; e < NBm; e++) acc[e] = bias;
        const float4* Wr = (const float4*)(Ws + L3 * 4096 + j * 64);
#pragma unroll
        for (int k4 = 0; k4 < 16; k4++) {
            float4 w = Wr[k4];
#pragma unroll
            for (int kk = 0; kk < 4; kk++) {
                int k = k4 * 4 + kk;
                float wv = (&w.x)[kk];
                float4 h0 = *(const float4*)&hb[pp][path][k][0];
                float4 h1 = *(const float4*)&hb[pp][path][k][4];
                float4 h2 = *(const float4*)&hb[pp][path][k][8];
                float4 h3 = *(const float4*)&hb[pp][path][k][12];
                acc[0] += wv * h0.x; acc[1] += wv * h0.y; acc[2] += wv * h0.z; acc[3] += wv * h0.w;
                acc[4] += wv * h1.x; acc[5] += wv * h1.y; acc[6] += wv * h1.z; acc[7] += wv * h1.w;
                acc[8] += wv * h2.x; acc[9] += wv * h2.y; acc[10] += wv * h2.z; acc[11] += wv * h2.w;
                acc[12] += wv * h3.x; acc[13] += wv * h3.y; acc[14] += wv * h3.z; acc[15] += wv * h3.w;
            }
        }
#pragma unroll
        for (int e = 0; e < NBm; e++) hb[pp ^ 1][path][j][e] = leaky(acc[e]);
        __syncthreads();
        pp ^= 1;
    }

    {
        const size_t muOff = (size_t)2 * B * 120 + (size_t)path * B * 100;
        int o2 = j + 64;
        bool v2 = (o2 < 100);
        float a1[NBm], a2[NBm];
        float b1 = bf[j], b2 = v2 ? bf[o2] : 0.0f;
#pragma unroll
        for (int e = 0; e < NBm; e++) { a1[e] = b1; a2[e] = b2; }
        const float4* W1 = (const float4*)(Wf + j * 64);
        const float4* W2 = (const float4*)(Wf + (v2 ? o2 : j) * 64);
#pragma unroll
        for (int k4 = 0; k4 < 16; k4++) {
            float4 w1 = W1[k4], w2 = W2[k4];
#pragma unroll
            for (int kk = 0; kk < 4; kk++) {
                int k = k4 * 4 + kk;
                float wv1 = (&w1.x)[kk], wv2 = (&w2.x)[kk];
#pragma unroll
                for (int q = 0; q < 4; q++) {
                    float4 hq = *(const float4*)&hb[pp][path][k][q * 4];
                    a1[q * 4 + 0] += wv1 * hq.x; a1[q * 4 + 1] += wv1 * hq.y;
                    a1[q * 4 + 2] += wv1 * hq.z; a1[q * 4 + 3] += wv1 * hq.w;
                    a2[q * 4 + 0] += wv2 * hq.x; a2[q * 4 + 1] += wv2 * hq.y;
                    a2[q * 4 + 2] += wv2 * hq.z; a2[q * 4 + 3] += wv2 * hq.w;
                }
            }
        }
#pragma unroll
        for (int e = 0; e < NBm; e++) {
            float f1 = leaky(a1[e]);
            fo_sh[path][j][e] = f1;
            out[muOff + (size_t)(b0 + e) * 100 + j] = f1;
            if (v2) {
                float f2 = leaky(a2[e]);
                fo_sh[path][o2][e] = f2;
                out[muOff + (size_t)(b0 + e) * 100 + o2] = f2;
            }
        }
    }
    __syncthreads();

    for (int idx = tid; idx < NBm * 100; idx += 128) {
        int e = idx / 100, o = idx - e * 100;
        float mu = fo_sh[0][o][e], lv = fo_sh[1][o][e];
        z_sh[e][o] = tanhfx(eps[(size_t)(b0 + e) * 100 + o] * __expf(0.5f * lv) + mu);
    }
    __syncthreads();

    {
        int half = tid >> 6;
        float acc8[8];
        float bi = binit[j];
#pragma unroll
        for (int e = 0; e < 8; e++) acc8[e] = bi;
        const float4* Wr = (const float4*)(Winit + j * 100);
#pragma unroll
        for (int o4 = 0; o4 < 25; o4++) {
            float4 w = Wr[o4];
#pragma unroll
            for (int e = 0; e < 8; e++) {
                float4 zv = *(const float4*)&z_sh[half * 8 + e][o4 * 4];
                acc8[e] += w.x * zv.x + w.y * zv.y + w.z * zv.z + w.w * zv.w;
            }
        }
#pragma unroll
        for (int e = 0; e < 8; e++)
            g_dh[(size_t)(b0 + half * 8 + e) * 64 + j] = acc8[e];
    }
}

// ---------------- decoder LSTM + bicycle dynamics ----------------
__global__ void __launch_bounds__(256, 2) dec_kernel(const float* __restrict__ init_state,
                                                     const float* __restrict__ W_c,
                                                     const float* __restrict__ b_c,
                                                     float* __restrict__ out, int B) {
    __shared__ unsigned long long h_sh[2][4][64][4];
    __shared__ float4 prev_sh[4][8];

    const int tid = threadIdx.x, g = tid >> 6, j = tid & 63;
    const int base = blockIdx.x * 32 + g * 8;

    float c[8], hv[8];
#pragma unroll
    for (int e = 0; e < 8; e++) {
        hv[e] = g_dh[(size_t)(base + e) * 64 + j];
        c[e] = hv[e];
    }
#pragma unroll
    for (int p = 0; p < 4; p++) h_sh[0][g][j][p] = pk2(hv[2 * p], hv[2 * p + 1]);
    if (j < 8) prev_sh[g][j] = *(const float4*)(init_state + (size_t)(base + j) * 4);
    __syncthreads();

    for (int t = 0; t < TT; t++) {
        const int cur = t & 1, nxt = cur ^ 1;
        unsigned long long acc[4][4];
        {
            float me0[4], me1[4], me2[4], me3[4], bb[4];
#pragma unroll
            for (int r = 0; r < 4; r++) {
                float4 m = g_Md4[r * 64 + j];
                me0[r] = m.x; me1[r] = m.y; me2[r] = m.z; me3[r] = m.w;
                bb[r] = g_bd[r * 64 + j];
            }
#pragma unroll
            for (int p = 0; p < 4; p++) {
                float4 i0 = prev_sh[g][2 * p], i1 = prev_sh[g][2 * p + 1];
#pragma unroll
                for (int r = 0; r < 4; r++) {
                    float a0 = bb[r] + me0[r] * i0.x + me1[r] * i0.y + me2[r] * i0.z + me3[r] * i0.w;
                    float a1 = bb[r] + me0[r] * i1.x + me1[r] * i1.y + me2[r] * i1.z + me3[r] * i1.w;
                    acc[r][p] = pk2(a0, a1);
                }
            }
        }
#pragma unroll 8
        for (int k = 0; k < 64; k++) {
            float4 w = g_Whh4_d[k * 64 + j];
            unsigned long long w0 = pk2(w.x, w.x), w1 = pk2(w.y, w.y);
            unsigned long long w2 = pk2(w.z, w.z), w3 = pk2(w.w, w.w);
            ulonglong2 hAB = *(const ulonglong2*)&h_sh[cur][g][k][0];
            ulonglong2 hCD = *(const ulonglong2*)&h_sh[cur][g][k][2];
            unsigned long long hp[4] = {hAB.x, hAB.y, hCD.x, hCD.y};
#pragma unroll
            for (int p = 0; p < 4; p++) {
                acc[0][p] = fma2(w0, hp[p], acc[0][p]);
                acc[1][p] = fma2(w1, hp[p], acc[1][p]);
                acc[2][p] = fma2(w2, hp[p], acc[2][p]);
                acc[3][p] = fma2(w3, hp[p], acc[3][p]);
            }
        }
#pragma unroll
        for (int p = 0; p < 4; p++) {
            float i0, i1, f0, f1, g0, g1, o0, o1;
            upk2(acc[0][p], i0, i1); upk2(acc[1][p], f0, f1);
            upk2(acc[2][p], g0, g1); upk2(acc[3][p], o0, o1);
            int e = 2 * p;
            float cn = sigf(f0) * c[e] + sigf(i0) * tanhfx(g0);
            hv[e] = sigf(o0) * tanhfx(cn); c[e] = cn;
            e++;
            cn = sigf(f1) * c[e] + sigf(i1) * tanhfx(g1);
            hv[e] = sigf(o1) * tanhfx(cn); c[e] = cn;
        }
#pragma unroll
        for (int p = 0; p < 4; p++) h_sh[nxt][g][j][p] = pk2(hv[2 * p], hv[2 * p + 1]);
        __syncthreads();  // h_sh[nxt] visible

        if (j < 16) {  // ctrl + shuffle exchange + dynamics, one phase
            int e = j >> 1, w = j & 1;
            float a = b_c[w];
            const float* hf = (const float*)&h_sh[nxt][g][0][0];  // [k][8] float view
            const float4* wc = (const float4*)(W_c + w * 64);
#pragma unroll
            for (int k4 = 0; k4 < 16; k4++) {
                float4 wv = wc[k4];
                int kb = k4 * 4;
                a += wv.x * hf[kb * 8 + e] + wv.y * hf[(kb + 1) * 8 + e] +
                     wv.z * hf[(kb + 2) * 8 + e] + wv.w * hf[(kb + 3) * 8 + e];
            }
            float other = __shfl_xor_sync(0xFFFFu, a, 1);
            if (w == 0) {  // a = pedal, other = raw steer
                float4 pv = prev_sh[g][e];
                float steer = fminf(fmaxf(other, -0.5f), 0.5f);
                float v1 = fminf(fmaxf(pv.w + a * DTc, 0.0f), 30.0f);
                float pd = fminf(fmaxf(pv.w * __tanf(steer) * 0.4f, -1.57f), 1.57f);
                float sn, cs;
                __sincosf(pv.z, &sn, &cs);
                float4 cur2 = make_float4(pv.x + pv.w * cs * DTc,
                                          pv.y + pv.w * sn * DTc,
                                          pv.z + pd * DTc, v1);
                prev_sh[g][e] = cur2;
                *(float4*)(out + (size_t)(base + e) * 120 + t * 4) = cur2;
            }
        }
        __syncthreads();  // prev_sh visible for next step
    }
}

// ---------------- launch ----------------
extern "C" void kernel_launch(void* const* d_in, const int* in_sizes, int n_in,
                              void* d_out, int out_size) {
    const float* traj   = (const float*)d_in[0];
    const float* init   = (const float*)d_in[1];
    const float* eps    = (const float*)d_in[2];
    const float* Wse    = (const float*)d_in[3];
    const float* bse    = (const float*)d_in[4];
    const float* Wih_e  = (const float*)d_in[5];
    const float* Whh_e  = (const float*)d_in[6];
    const float* bih_e  = (const float*)d_in[7];
    const float* bhh_e  = (const float*)d_in[8];
    const float* mWs    = (const float*)d_in[9];
    const float* mbs    = (const float*)d_in[10];
    const float* mWf    = (const float*)d_in[11];
    const float* mbf    = (const float*)d_in[12];
    const float* lWs    = (const float*)d_in[13];
    const float* lbs    = (const float*)d_in[14];
    const float* lWf    = (const float*)d_in[15];
    const float* lbf    = (const float*)d_in[16];
    const float* Winit  = (const float*)d_in[17];
    const float* binit  = (const float*)d_in[18];
    const float* Wih_d  = (const float*)d_in[19];
    const float* Whh_d  = (const float*)d_in[20];
    const float* bih_d  = (const float*)d_in[21];
    const float* bhh_d  = (const float*)d_in[22];
    const float* Wc     = (const float*)d_in[23];
    const float* bc     = (const float*)d_in[24];
    float* out = (float*)d_out;

    int B = in_sizes[0] / 120;  // (B, 30, 4)

    prep_kernel<<<1, 256>>>(Wse, bse, Wih_e, Whh_e, bih_e, bhh_e,
                            Wih_d, Whh_d, bih_d, bhh_d);
    enc_kernel<<<B / 32, 256>>>(traj, B);
    mlp_kernel<<<B / NBm, 128>>>(eps, mWs, mbs, mWf, mbf, lWs, lbs, lWf, lbf,
                                 Winit, binit, out, B);
    dec_kernel<<<B / 32, 256>>>(init, Wc, bc, out, B);
    // expert_traj passthrough (output slot 2)
    cudaMemcpyAsync(out + (size_t)B * 120, traj, (size_t)B * 120 * sizeof(float),
                    cudaMemcpyDeviceToDevice);
}